// round 1
// baseline (speedup 1.0000x reference)
#include <cuda_runtime.h>
#include <math.h>

#define BB  16
#define CC  64
#define HH  128
#define WW  128
#define HW  (HH*WW)
#define BC  (BB*CC)

// Per-(b,c) sigmoid-max threshold M = ps - 0.01, produced by k1, consumed by k2.
__device__ float g_M[BC];

__device__ __forceinline__ float sigmoidf_(float v) {
    return 1.0f / (1.0f + expf(-v));
}

// ---------------------------------------------------------------------------
// K1: per-(b,c) plane. Computes ps, M, sparse masked sums, writes bbox row.
// ---------------------------------------------------------------------------
__global__ __launch_bounds__(256) void k1_stats(
    const float* __restrict__ x,
    const float* __restrict__ w_bbx,
    const float* __restrict__ w_width,
    const float* __restrict__ w_width_sh,
    const float* __restrict__ w_height,
    const float* __restrict__ w_height_sh,
    float* __restrict__ out)
{
    extern __shared__ float xs[];   // HW floats = 64 KB
    const int bc = blockIdx.x;
    const int b  = bc / CC;
    const int c  = bc % CC;
    const float* xp = x + (size_t)bc * HW;
    const int t = threadIdx.x;

    // pass 1: load plane, track max sigmoid
    float mx = -INFINITY;
    #pragma unroll 4
    for (int i = t; i < HW; i += 256) {
        float v = xp[i];
        xs[i] = v;
        mx = fmaxf(mx, sigmoidf_(v));
    }
    __shared__ float red[8];
    #pragma unroll
    for (int o = 16; o; o >>= 1) mx = fmaxf(mx, __shfl_xor_sync(0xffffffffu, mx, o));
    if ((t & 31) == 0) red[t >> 5] = mx;
    __syncthreads();
    float ps;
    {
        float v = red[0];
        #pragma unroll
        for (int k = 1; k < 8; ++k) v = fmaxf(v, red[k]);
        ps = v;
    }
    const float M = ps - 0.01f;

    // per-channel conv coefficients
    float cw[11], ch[11];
    #pragma unroll
    for (int k = 0; k < 11; ++k) { cw[k] = w_width[c*11+k]; ch[k] = w_height[c*11+k]; }
    const float s0 = w_bbx[c] * 128.0f;
    const float sW = s0 * w_width_sh[c];
    const float sH = s0 * w_height_sh[c];

    // pass 2: masked sums; convs evaluated only at (rare) masked pixels
    float S = 0.f, Sc = 0.f, Sr = 0.f, Sw = 0.f, Sh = 0.f;
    for (int i = t; i < HW; i += 256) {
        float v = xs[i];
        float s = sigmoidf_(v);
        if (s > M) {
            int row = i >> 7, col = i & 127;
            S  += v;
            Sc += (float)col * v;
            Sr += (float)row * v;
            float wv = 0.f;
            #pragma unroll
            for (int k = 0; k < 11; ++k) {
                int cc2 = col - 5 + k;
                if (cc2 >= 0 && cc2 < WW) wv = fmaf(xs[(row << 7) + cc2], cw[k], wv);
            }
            float hv = 0.f;
            #pragma unroll
            for (int k = 0; k < 11; ++k) {
                int rr = row - 5 + k;
                if (rr >= 0 && rr < HH) hv = fmaf(xs[(rr << 7) + col], ch[k], hv);
            }
            Sw += wv * sW * v;
            Sh += hv * sH * v;
        }
    }
    // block reduce 5 sums
    __shared__ float racc[5][8];
    #pragma unroll
    for (int o = 16; o; o >>= 1) {
        S  += __shfl_xor_sync(0xffffffffu, S,  o);
        Sc += __shfl_xor_sync(0xffffffffu, Sc, o);
        Sr += __shfl_xor_sync(0xffffffffu, Sr, o);
        Sw += __shfl_xor_sync(0xffffffffu, Sw, o);
        Sh += __shfl_xor_sync(0xffffffffu, Sh, o);
    }
    if ((t & 31) == 0) {
        int w5 = t >> 5;
        racc[0][w5] = S; racc[1][w5] = Sc; racc[2][w5] = Sr; racc[3][w5] = Sw; racc[4][w5] = Sh;
    }
    __syncthreads();
    if (t == 0) {
        float a0=0,a1=0,a2=0,a3=0,a4=0;
        #pragma unroll
        for (int k = 0; k < 8; ++k) { a0+=racc[0][k]; a1+=racc[1][k]; a2+=racc[2][k]; a3+=racc[3][k]; a4+=racc[4][k]; }
        float ws = a3 / a0, hs = a4 / a0;
        float x1 = a1 / a0 - ws * 0.5f;
        float y1 = a2 / a0 - hs * 0.5f;
        float* bb = out + (size_t)BB * 3 * CC * HW + (size_t)bc * 6;
        bb[0] = (float)b; bb[1] = x1; bb[2] = y1;
        bb[3] = x1 + ws;  bb[4] = y1 + hs; bb[5] = ps;
        g_M[bc] = M;
    }
}

// ---------------------------------------------------------------------------
// K2: per (b, 8-row group). Loops all 64 channels twice: sweep 0 tracks
// per-pixel channel maxes of (score, w, h); sweep 1 recomputes (identical
// code => identical bits) and writes val*(val==max).
// ---------------------------------------------------------------------------
#define TROWS 18          // 8 output rows + 2*5 halo
#define TPITCH 144        // 8 zero-pad | 128 data | 8 zero-pad

__global__ __launch_bounds__(256) void k2_mask(
    const float* __restrict__ x,
    const float* __restrict__ w_bbx,
    const float* __restrict__ w_width,
    const float* __restrict__ w_width_sh,
    const float* __restrict__ w_height,
    const float* __restrict__ w_height_sh,
    float* __restrict__ out)
{
    __shared__ float tile[TROWS * TPITCH];
    __shared__ float scw[CC * 11], sch[CC * 11];
    __shared__ float ssW[CC], ssH[CC], sM[CC];

    const int t    = threadIdx.x;
    const int b    = blockIdx.y;
    const int rg   = blockIdx.x;        // 0..15
    const int row0 = rg * 8;
    const int r    = t >> 5;            // 0..7 : output row within group
    const int c4   = (t & 31) << 2;     // 0..124 : first of 4 output cols
    const int lrow = r + 5;             // local tile row of the output row
    const int grow = row0 + r;

    // zero pads once (never overwritten by data fills)
    for (int i = t; i < TROWS * TPITCH; i += 256) {
        int col = i % TPITCH;
        if (col < 8 || col >= 136) tile[i] = 0.f;
    }
    // stage all channel coefficients / scales / thresholds
    for (int i = t; i < CC * 11; i += 256) { scw[i] = w_width[i]; sch[i] = w_height[i]; }
    if (t < CC) {
        float s0 = w_bbx[t] * 128.0f;
        ssW[t] = s0 * w_width_sh[t];
        ssH[t] = s0 * w_height_sh[t];
        sM[t]  = g_M[b * CC + t];
    }

    float mS[4], mW[4], mH[4];
    #pragma unroll
    for (int j = 0; j < 4; ++j) { mS[j] = -INFINITY; mW[j] = -INFINITY; mH[j] = -INFINITY; }

    for (int phase = 0; phase < 2; ++phase) {
        for (int c = 0; c < CC; ++c) {
            __syncthreads();   // previous tile fully consumed / coef writes visible
            const float* xp = x + ((size_t)(b * CC + c)) * HW;
            // fill 18x128 data region (zero rows outside the image)
            #pragma unroll
            for (int j = 0; j < 9; ++j) {
                int idx = t + j * 256;
                int jr = idx >> 7, col = idx & 127;
                int gr = row0 - 5 + jr;
                tile[jr * TPITCH + 8 + col] = (gr >= 0 && gr < HH) ? xp[(gr << 7) + col] : 0.f;
            }
            __syncthreads();

            // horizontal input window: cols [c4-8, c4+12)  (5 aligned float4)
            float in[20];
            const float* hrow = &tile[lrow * TPITCH + c4];   // data starts at +8, so this is col c4-8
            #pragma unroll
            for (int m = 0; m < 5; ++m) {
                float4 v = *(const float4*)(hrow + 4 * m);
                in[4*m+0] = v.x; in[4*m+1] = v.y; in[4*m+2] = v.z; in[4*m+3] = v.w;
            }
            // vertical conv accumulation for the 4 columns
            float hv0 = 0.f, hv1 = 0.f, hv2 = 0.f, hv3 = 0.f;
            #pragma unroll
            for (int k = 0; k < 11; ++k) {
                float4 v = *(const float4*)(&tile[(r + k) * TPITCH + 8 + c4]);
                float ck = sch[c * 11 + k];
                hv0 = fmaf(v.x, ck, hv0);
                hv1 = fmaf(v.y, ck, hv1);
                hv2 = fmaf(v.z, ck, hv2);
                hv3 = fmaf(v.w, ck, hv3);
            }
            const float sWc = ssW[c], sHc = ssH[c], Mc = sM[c];
            float oS[4], oW[4], oH[4];
            #pragma unroll
            for (int j = 0; j < 4; ++j) {
                float wv = 0.f;
                #pragma unroll
                for (int k = 0; k < 11; ++k) wv = fmaf(in[3 + j + k], scw[c * 11 + k], wv);
                wv *= sWc;
                float hv = (j == 0 ? hv0 : j == 1 ? hv1 : j == 2 ? hv2 : hv3) * sHc;
                float xv = in[8 + j];
                float s  = sigmoidf_(xv);
                float sc = (s > Mc) ? xv : 0.f;
                if (phase == 0) {
                    mS[j] = fmaxf(mS[j], sc);
                    mW[j] = fmaxf(mW[j], wv);
                    mH[j] = fmaxf(mH[j], hv);
                } else {
                    oS[j] = (sc == mS[j]) ? sc : 0.f;
                    oW[j] = (wv == mW[j]) ? wv : 0.f;
                    oH[j] = (hv == mH[j]) ? hv : 0.f;
                }
            }
            if (phase == 1) {
                size_t base = ((size_t)b * (3 * CC) + c) * HW + ((size_t)grow << 7) + c4;
                *(float4*)(out + base)                       = make_float4(oS[0], oS[1], oS[2], oS[3]);
                *(float4*)(out + base + (size_t)CC * HW)     = make_float4(oW[0], oW[1], oW[2], oW[3]);
                *(float4*)(out + base + (size_t)2 * CC * HW) = make_float4(oH[0], oH[1], oH[2], oH[3]);
            }
        }
    }
}

extern "C" void kernel_launch(void* const* d_in, const int* in_sizes, int n_in,
                              void* d_out, int out_size)
{
    const float* x           = (const float*)d_in[0];
    const float* w_bbx       = (const float*)d_in[1];
    const float* w_width     = (const float*)d_in[2];
    const float* w_width_sh  = (const float*)d_in[3];
    const float* w_height    = (const float*)d_in[4];
    const float* w_height_sh = (const float*)d_in[5];
    float* out = (float*)d_out;

    cudaFuncSetAttribute(k1_stats, cudaFuncAttributeMaxDynamicSharedMemorySize, HW * (int)sizeof(float));
    k1_stats<<<BC, 256, HW * sizeof(float)>>>(x, w_bbx, w_width, w_width_sh, w_height, w_height_sh, out);

    dim3 g2(16, BB);
    k2_mask<<<g2, 256>>>(x, w_bbx, w_width, w_width_sh, w_height, w_height_sh, out);
}

// round 3
// speedup vs baseline: 1.7810x; 1.7810x over previous
#include <cuda_runtime.h>
#include <math.h>

#define BB  16
#define CC  64
#define HH  128
#define WW  128
#define HW  (HH*WW)
#define BC  (BB*CC)

// Per-(b,c) x-space threshold T = logit(sigmoid(max x) - 0.01), from k1.
__device__ float g_T[BC];
// Per-pixel channel maxes of score / w / h (filled by k2a, read by k2b).
__device__ float g_maxS[BB * HW];
__device__ float g_maxW[BB * HW];
__device__ float g_maxH[BB * HW];

__device__ __forceinline__ float sigmoidf_(float v) {
    return 1.0f / (1.0f + expf(-v));
}

// ---------------------------------------------------------------------------
// K1: per-(b,c) plane. max(x) -> ps, threshold T; masked sums -> bbox row.
// ---------------------------------------------------------------------------
__global__ __launch_bounds__(256) void k1_stats(
    const float* __restrict__ x,
    const float* __restrict__ w_bbx,
    const float* __restrict__ w_width,
    const float* __restrict__ w_width_sh,
    const float* __restrict__ w_height,
    const float* __restrict__ w_height_sh,
    float* __restrict__ out)
{
    const int bc = blockIdx.x;
    const int b  = bc / CC;
    const int c  = bc % CC;
    const float* __restrict__ xp = x + (size_t)bc * HW;
    const int t = threadIdx.x;

    // pass 1: plain max of x (sigmoid is monotone)
    float mx = -INFINITY;
    #pragma unroll
    for (int j = 0; j < 16; ++j) {
        float4 v = *(const float4*)(xp + 1024 * j + 4 * t);
        mx = fmaxf(fmaxf(fmaxf(mx, v.x), fmaxf(v.y, v.z)), v.w);
    }
    __shared__ float red[8];
    #pragma unroll
    for (int o = 16; o; o >>= 1) mx = fmaxf(mx, __shfl_xor_sync(0xffffffffu, mx, o));
    if ((t & 31) == 0) red[t >> 5] = mx;
    __syncthreads();
    __shared__ float sT, sps;
    if (t == 0) {
        float v = red[0];
        #pragma unroll
        for (int k = 1; k < 8; ++k) v = fmaxf(v, red[k]);
        float ps = sigmoidf_(v);
        float M  = ps - 0.01f;
        float T;
        if (M > 0.0f) {
            double dM = (double)M;
            T = (float)log(dM / (1.0 - dM));
        } else {
            T = -INFINITY;
        }
        sT = T; sps = ps;
        g_T[bc] = T;
    }
    __syncthreads();
    const float T = sT;

    float cw[11], ch[11];
    #pragma unroll
    for (int k = 0; k < 11; ++k) { cw[k] = w_width[c*11+k]; ch[k] = w_height[c*11+k]; }
    const float s0 = w_bbx[c] * 128.0f;
    const float sW = s0 * w_width_sh[c];
    const float sH = s0 * w_height_sh[c];

    // pass 2: masked sums; convs only at (rare) masked pixels (L2 reads)
    float S = 0.f, Sc = 0.f, Sr = 0.f, Sw = 0.f, Sh = 0.f;
    for (int i = t; i < HW; i += 256) {
        float v = __ldg(xp + i);
        if (v > T) {
            int row = i >> 7, col = i & 127;
            S  += v;
            Sc += (float)col * v;
            Sr += (float)row * v;
            float wv = 0.f;
            #pragma unroll
            for (int k = 0; k < 11; ++k) {
                int cc2 = col - 5 + k;
                if (cc2 >= 0 && cc2 < WW) wv = fmaf(xp[(row << 7) + cc2], cw[k], wv);
            }
            float hv = 0.f;
            #pragma unroll
            for (int k = 0; k < 11; ++k) {
                int rr = row - 5 + k;
                if (rr >= 0 && rr < HH) hv = fmaf(xp[(rr << 7) + col], ch[k], hv);
            }
            Sw += wv * sW * v;
            Sh += hv * sH * v;
        }
    }
    __shared__ float racc[5][8];
    #pragma unroll
    for (int o = 16; o; o >>= 1) {
        S  += __shfl_xor_sync(0xffffffffu, S,  o);
        Sc += __shfl_xor_sync(0xffffffffu, Sc, o);
        Sr += __shfl_xor_sync(0xffffffffu, Sr, o);
        Sw += __shfl_xor_sync(0xffffffffu, Sw, o);
        Sh += __shfl_xor_sync(0xffffffffu, Sh, o);
    }
    if ((t & 31) == 0) {
        int w5 = t >> 5;
        racc[0][w5] = S; racc[1][w5] = Sc; racc[2][w5] = Sr; racc[3][w5] = Sw; racc[4][w5] = Sh;
    }
    __syncthreads();
    if (t == 0) {
        float a0=0,a1=0,a2=0,a3=0,a4=0;
        #pragma unroll
        for (int k = 0; k < 8; ++k) { a0+=racc[0][k]; a1+=racc[1][k]; a2+=racc[2][k]; a3+=racc[3][k]; a4+=racc[4][k]; }
        float ws = a3 / a0, hs = a4 / a0;
        float x1 = a1 / a0 - ws * 0.5f;
        float y1 = a2 / a0 - hs * 0.5f;
        float* bb = out + (size_t)BB * 3 * CC * HW + (size_t)bc * 6;
        bb[0] = (float)b; bb[1] = x1; bb[2] = y1;
        bb[3] = x1 + ws;  bb[4] = y1 + hs; bb[5] = sps;
    }
}

// ---------------------------------------------------------------------------
// K2a: dense w/h/score, written unmasked to out; per-pixel channel maxes to
// g_max*. One barrier per channel via double-buffered smem tile.
// 128 threads: r = t>>5 (4 rows), c4 = (t&31)<<2 (4 cols, 16B-aligned).
// ---------------------------------------------------------------------------
#define RG 4              // rows per block
#define TR 14             // RG + 2*5 halo
#define TP 144            // 8 zero-pad | 128 data | 8 zero-pad   (all mult of 4)

__global__ __launch_bounds__(128) void k2a_dense(
    const float* __restrict__ x,
    const float* __restrict__ w_bbx,
    const float* __restrict__ w_width,
    const float* __restrict__ w_width_sh,
    const float* __restrict__ w_height,
    const float* __restrict__ w_height_sh,
    float* __restrict__ out)
{
    __shared__ float tile[2][TR * TP];
    __shared__ float scw[CC * 11], sch[CC * 11];
    __shared__ float ssW[CC], ssH[CC], sTv[CC];

    const int t    = threadIdx.x;         // 0..127
    const int b    = blockIdx.y;
    const int rg   = blockIdx.x;          // 0..31
    const int row0 = rg * RG;
    const int r    = t >> 5;              // 0..3
    const int c4   = (t & 31) << 2;       // 0..124, multiple of 4
    const int grow = row0 + r;

    // zero pads once for both buffers (fills never touch them)
    for (int i = t; i < TR * TP; i += 128) {
        int col = i % TP;
        if (col < 8 || col >= 136) { tile[0][i] = 0.f; tile[1][i] = 0.f; }
    }
    for (int i = t; i < CC * 11; i += 128) { scw[i] = w_width[i]; sch[i] = w_height[i]; }
    if (t < CC) {
        float s0 = w_bbx[t] * 128.0f;
        ssW[t] = s0 * w_width_sh[t];
        ssH[t] = s0 * w_height_sh[t];
        sTv[t] = g_T[b * CC + t];
    }

    // fill staging: 14 elements per thread cover 14x128
    int   fjr[14], fcol[14];
    bool  fok[14];
    #pragma unroll
    for (int j = 0; j < 14; ++j) {
        int idx = t + j * 128;
        fjr[j]  = idx >> 7;
        fcol[j] = idx & 127;
        int gr  = row0 - 5 + fjr[j];
        fok[j]  = (gr >= 0 && gr < HH);
    }
    const int gbase0 = (row0 - 5) << 7;   // global offset of tile row 0 (may be negative)

    float regs[14];
    const float* xp0 = x + (size_t)(b * CC) * HW;

    // prologue: stage + store channel 0
    {
        const float* xp = xp0;
        #pragma unroll
        for (int j = 0; j < 14; ++j)
            regs[j] = fok[j] ? __ldg(xp + gbase0 + (fjr[j] << 7) + fcol[j]) : 0.f;
        #pragma unroll
        for (int j = 0; j < 14; ++j)
            tile[0][fjr[j] * TP + 8 + fcol[j]] = regs[j];
    }

    float mS[4], mW[4], mH[4];
    #pragma unroll
    for (int j = 0; j < 4; ++j) { mS[j] = -INFINITY; mW[j] = -INFINITY; mH[j] = -INFINITY; }

    for (int c = 0; c < CC; ++c) {
        const int cur = c & 1;
        // stage next channel (LDGs overlap barrier + compute)
        if (c + 1 < CC) {
            const float* xp = xp0 + (size_t)(c + 1) * HW;
            #pragma unroll
            for (int j = 0; j < 14; ++j)
                regs[j] = fok[j] ? __ldg(xp + gbase0 + (fjr[j] << 7) + fcol[j]) : 0.f;
        }
        __syncthreads();   // tile[cur] fully stored; tile[cur^1] fully consumed

        const float* tl = tile[cur];
        // horizontal window: cols [c4-8, c4+12) = 5 aligned float4 (data at +8)
        float in[20];
        {
            const float* hrow = &tl[(r + 5) * TP + c4];  // col c4-8 of data
            #pragma unroll
            for (int m = 0; m < 5; ++m) {
                float4 v = *(const float4*)(hrow + 4 * m);
                in[4*m+0] = v.x; in[4*m+1] = v.y; in[4*m+2] = v.z; in[4*m+3] = v.w;
            }
        }
        // vertical conv for the 4 columns
        float hv[4] = {0.f, 0.f, 0.f, 0.f};
        #pragma unroll
        for (int k = 0; k < 11; ++k) {
            float4 v = *(const float4*)(&tl[(r + k) * TP + 8 + c4]);
            float ck = sch[c * 11 + k];
            hv[0] = fmaf(v.x, ck, hv[0]);
            hv[1] = fmaf(v.y, ck, hv[1]);
            hv[2] = fmaf(v.z, ck, hv[2]);
            hv[3] = fmaf(v.w, ck, hv[3]);
        }
        // horizontal conv: output col c4+j uses in[3+j .. 13+j]
        float wv[4] = {0.f, 0.f, 0.f, 0.f};
        #pragma unroll
        for (int k = 0; k < 11; ++k) {
            float ck = scw[c * 11 + k];
            wv[0] = fmaf(in[3 + k], ck, wv[0]);
            wv[1] = fmaf(in[4 + k], ck, wv[1]);
            wv[2] = fmaf(in[5 + k], ck, wv[2]);
            wv[3] = fmaf(in[6 + k], ck, wv[3]);
        }
        const float sWc = ssW[c], sHc = ssH[c], Tc = sTv[c];
        float sc[4];
        #pragma unroll
        for (int j = 0; j < 4; ++j) {
            wv[j] *= sWc;
            hv[j] *= sHc;
            float xv = in[8 + j];
            sc[j] = (xv > Tc) ? xv : 0.f;
            mS[j] = fmaxf(mS[j], sc[j]);
            mW[j] = fmaxf(mW[j], wv[j]);
            mH[j] = fmaxf(mH[j], hv[j]);
        }

        size_t base = ((size_t)(b * 3 * CC) + c) * HW + ((size_t)grow << 7) + c4;
        *(float4*)(out + base)                       = make_float4(sc[0], sc[1], sc[2], sc[3]);
        *(float4*)(out + base + (size_t)CC * HW)     = make_float4(wv[0], wv[1], wv[2], wv[3]);
        *(float4*)(out + base + (size_t)2 * CC * HW) = make_float4(hv[0], hv[1], hv[2], hv[3]);

        if (c + 1 < CC) {
            float* tn = tile[cur ^ 1];
            #pragma unroll
            for (int j = 0; j < 14; ++j)
                tn[fjr[j] * TP + 8 + fcol[j]] = regs[j];
        }
    }

    size_t mb = (size_t)b * HW + ((size_t)grow << 7) + c4;
    *(float4*)(g_maxS + mb) = make_float4(mS[0], mS[1], mS[2], mS[3]);
    *(float4*)(g_maxW + mb) = make_float4(mW[0], mW[1], mW[2], mW[3]);
    *(float4*)(g_maxH + mb) = make_float4(mH[0], mH[1], mH[2], mH[3]);
}

// ---------------------------------------------------------------------------
// K2b: streaming mask pass. val = (val == channel_max) ? val : 0.
// ---------------------------------------------------------------------------
__global__ __launch_bounds__(256) void k2b_mask(float* __restrict__ out)
{
    const int t  = threadIdx.x;
    const int bc = blockIdx.y;           // 0..1023
    const int b  = bc >> 6;
    const int c  = bc & 63;
    const int p4 = blockIdx.x * 256 + t; // 0..4095
    const size_t pix = (size_t)p4 << 2;

    const size_t mb = (size_t)b * HW + pix;
    float4 mS = *(const float4*)(g_maxS + mb);
    float4 mW = *(const float4*)(g_maxW + mb);
    float4 mH = *(const float4*)(g_maxH + mb);

    size_t baseS = ((size_t)(b * 3 * CC) + c) * HW + pix;
    size_t baseW = baseS + (size_t)CC * HW;
    size_t baseH = baseS + (size_t)2 * CC * HW;

    float4 vS = *(const float4*)(out + baseS);
    float4 vW = *(const float4*)(out + baseW);
    float4 vH = *(const float4*)(out + baseH);

    vS.x = (vS.x == mS.x) ? vS.x : 0.f;
    vS.y = (vS.y == mS.y) ? vS.y : 0.f;
    vS.z = (vS.z == mS.z) ? vS.z : 0.f;
    vS.w = (vS.w == mS.w) ? vS.w : 0.f;
    vW.x = (vW.x == mW.x) ? vW.x : 0.f;
    vW.y = (vW.y == mW.y) ? vW.y : 0.f;
    vW.z = (vW.z == mW.z) ? vW.z : 0.f;
    vW.w = (vW.w == mW.w) ? vW.w : 0.f;
    vH.x = (vH.x == mH.x) ? vH.x : 0.f;
    vH.y = (vH.y == mH.y) ? vH.y : 0.f;
    vH.z = (vH.z == mH.z) ? vH.z : 0.f;
    vH.w = (vH.w == mH.w) ? vH.w : 0.f;

    *(float4*)(out + baseS) = vS;
    *(float4*)(out + baseW) = vW;
    *(float4*)(out + baseH) = vH;
}

extern "C" void kernel_launch(void* const* d_in, const int* in_sizes, int n_in,
                              void* d_out, int out_size)
{
    const float* x           = (const float*)d_in[0];
    const float* w_bbx       = (const float*)d_in[1];
    const float* w_width     = (const float*)d_in[2];
    const float* w_width_sh  = (const float*)d_in[3];
    const float* w_height    = (const float*)d_in[4];
    const float* w_height_sh = (const float*)d_in[5];
    float* out = (float*)d_out;

    k1_stats<<<BC, 256>>>(x, w_bbx, w_width, w_width_sh, w_height, w_height_sh, out);

    dim3 g2(32, BB);
    k2a_dense<<<g2, 128>>>(x, w_bbx, w_width, w_width_sh, w_height, w_height_sh, out);

    dim3 g3(16, BB * CC);
    k2b_mask<<<g3, 256>>>(out);
}

// round 4
// speedup vs baseline: 1.7871x; 1.0034x over previous
#include <cuda_runtime.h>
#include <math.h>

#define BB  16
#define CC  64
#define HH  128
#define WW  128
#define HW  (HH*WW)
#define BC  (BB*CC)

// Per-(b,c) x-space threshold T = logit(sigmoid(max x) - 0.01), from k1.
__device__ float g_T[BC];
// Per-pixel channel maxes of score / w / h (filled by k2a, read by k2b).
__device__ float g_maxS[BB * HW];
__device__ float g_maxW[BB * HW];
__device__ float g_maxH[BB * HW];

__device__ __forceinline__ float sigmoidf_(float v) {
    return 1.0f / (1.0f + expf(-v));
}

// ---------------------------------------------------------------------------
// K1: per-(b,c) plane. max(x) -> ps, threshold T; masked sums -> bbox row.
// Both passes use float4 loads (MLP >= 16).
// ---------------------------------------------------------------------------
__global__ __launch_bounds__(256) void k1_stats(
    const float* __restrict__ x,
    const float* __restrict__ w_bbx,
    const float* __restrict__ w_width,
    const float* __restrict__ w_width_sh,
    const float* __restrict__ w_height,
    const float* __restrict__ w_height_sh,
    float* __restrict__ out)
{
    const int bc = blockIdx.x;
    const int b  = bc / CC;
    const int c  = bc % CC;
    const float* __restrict__ xp = x + (size_t)bc * HW;
    const int t = threadIdx.x;

    // pass 1: plain max of x (sigmoid is monotone)
    float mx = -INFINITY;
    #pragma unroll
    for (int j = 0; j < 16; ++j) {
        float4 v = *(const float4*)(xp + 1024 * j + 4 * t);
        mx = fmaxf(fmaxf(fmaxf(mx, v.x), fmaxf(v.y, v.z)), v.w);
    }
    __shared__ float red[8];
    #pragma unroll
    for (int o = 16; o; o >>= 1) mx = fmaxf(mx, __shfl_xor_sync(0xffffffffu, mx, o));
    if ((t & 31) == 0) red[t >> 5] = mx;
    __syncthreads();
    __shared__ float sT, sps;
    if (t == 0) {
        float v = red[0];
        #pragma unroll
        for (int k = 1; k < 8; ++k) v = fmaxf(v, red[k]);
        float ps = sigmoidf_(v);
        float M  = ps - 0.01f;
        float T;
        if (M > 0.0f) {
            double dM = (double)M;
            T = (float)log(dM / (1.0 - dM));
        } else {
            T = -INFINITY;
        }
        sT = T; sps = ps;
        g_T[bc] = T;
    }
    __syncthreads();
    const float T = sT;

    float cw[11], ch[11];
    #pragma unroll
    for (int k = 0; k < 11; ++k) { cw[k] = w_width[c*11+k]; ch[k] = w_height[c*11+k]; }
    const float s0 = w_bbx[c] * 128.0f;
    const float sW = s0 * w_width_sh[c];
    const float sH = s0 * w_height_sh[c];

    // pass 2: float4 scan, scalar conv work only at (rare) masked pixels
    float S = 0.f, Sc = 0.f, Sr = 0.f, Sw = 0.f, Sh = 0.f;
    #pragma unroll
    for (int j = 0; j < 16; ++j) {
        const int i0 = 1024 * j + 4 * t;
        float4 v4 = *(const float4*)(xp + i0);
        float vv[4] = {v4.x, v4.y, v4.z, v4.w};
        if (vv[0] > T || vv[1] > T || vv[2] > T || vv[3] > T) {
            #pragma unroll
            for (int u = 0; u < 4; ++u) {
                float v = vv[u];
                if (v > T) {
                    int i = i0 + u;
                    int row = i >> 7, col = i & 127;
                    S  += v;
                    Sc += (float)col * v;
                    Sr += (float)row * v;
                    float wvv = 0.f;
                    #pragma unroll
                    for (int k = 0; k < 11; ++k) {
                        int cc2 = col - 5 + k;
                        if (cc2 >= 0 && cc2 < WW) wvv = fmaf(xp[(row << 7) + cc2], cw[k], wvv);
                    }
                    float hvv = 0.f;
                    #pragma unroll
                    for (int k = 0; k < 11; ++k) {
                        int rr = row - 5 + k;
                        if (rr >= 0 && rr < HH) hvv = fmaf(xp[(rr << 7) + col], ch[k], hvv);
                    }
                    Sw += wvv * sW * v;
                    Sh += hvv * sH * v;
                }
            }
        }
    }
    __shared__ float racc[5][8];
    #pragma unroll
    for (int o = 16; o; o >>= 1) {
        S  += __shfl_xor_sync(0xffffffffu, S,  o);
        Sc += __shfl_xor_sync(0xffffffffu, Sc, o);
        Sr += __shfl_xor_sync(0xffffffffu, Sr, o);
        Sw += __shfl_xor_sync(0xffffffffu, Sw, o);
        Sh += __shfl_xor_sync(0xffffffffu, Sh, o);
    }
    if ((t & 31) == 0) {
        int w5 = t >> 5;
        racc[0][w5] = S; racc[1][w5] = Sc; racc[2][w5] = Sr; racc[3][w5] = Sw; racc[4][w5] = Sh;
    }
    __syncthreads();
    if (t == 0) {
        float a0=0,a1=0,a2=0,a3=0,a4=0;
        #pragma unroll
        for (int k = 0; k < 8; ++k) { a0+=racc[0][k]; a1+=racc[1][k]; a2+=racc[2][k]; a3+=racc[3][k]; a4+=racc[4][k]; }
        float ws = a3 / a0, hs = a4 / a0;
        float x1 = a1 / a0 - ws * 0.5f;
        float y1 = a2 / a0 - hs * 0.5f;
        float* bb = out + (size_t)BB * 3 * CC * HW + (size_t)bc * 6;
        bb[0] = (float)b; bb[1] = x1; bb[2] = y1;
        bb[3] = x1 + ws;  bb[4] = y1 + hs; bb[5] = sps;
    }
}

// ---------------------------------------------------------------------------
// K2a: dense w/h/score written unmasked to out; per-pixel channel maxes to
// g_max*. One barrier per channel via double-buffered smem tile.
// 256 threads: r = t>>5 (8 rows), c4 = (t&31)<<2 (4 cols, 16B-aligned).
// ---------------------------------------------------------------------------
#define RG 8              // rows per block
#define TR 18             // RG + 2*5 halo
#define TP 144            // 8 zero-pad | 128 data | 8 zero-pad   (mult of 4)
#define NFILL 9           // TR*128 / 256

__global__ __launch_bounds__(256) void k2a_dense(
    const float* __restrict__ x,
    const float* __restrict__ w_bbx,
    const float* __restrict__ w_width,
    const float* __restrict__ w_width_sh,
    const float* __restrict__ w_height,
    const float* __restrict__ w_height_sh,
    float* __restrict__ out)
{
    __shared__ float tile[2][TR * TP];
    __shared__ float scw[CC * 11], sch[CC * 11];
    __shared__ float ssW[CC], ssH[CC], sTv[CC];

    const int t    = threadIdx.x;         // 0..255
    const int b    = blockIdx.y;
    const int rg   = blockIdx.x;          // 0..15
    const int row0 = rg * RG;
    const int r    = t >> 5;              // 0..7
    const int c4   = (t & 31) << 2;       // 0..124, multiple of 4
    const int grow = row0 + r;

    // zero pads once for both buffers (fills never touch them)
    for (int i = t; i < TR * TP; i += 256) {
        int col = i % TP;
        if (col < 8 || col >= 136) { tile[0][i] = 0.f; tile[1][i] = 0.f; }
    }
    for (int i = t; i < CC * 11; i += 256) { scw[i] = w_width[i]; sch[i] = w_height[i]; }
    if (t < CC) {
        float s0 = w_bbx[t] * 128.0f;
        ssW[t] = s0 * w_width_sh[t];
        ssH[t] = s0 * w_height_sh[t];
        sTv[t] = g_T[b * CC + t];
    }

    // fill staging: NFILL elements per thread cover TR x 128
    int   fjr[NFILL], fcol[NFILL];
    bool  fok[NFILL];
    #pragma unroll
    for (int j = 0; j < NFILL; ++j) {
        int idx = t + j * 256;
        fjr[j]  = idx >> 7;
        fcol[j] = idx & 127;
        int gr  = row0 - 5 + fjr[j];
        fok[j]  = (gr >= 0 && gr < HH);
    }
    const int gbase0 = (row0 - 5) << 7;   // global offset of tile row 0 (may be negative)

    float regs[NFILL];
    const float* xp0 = x + (size_t)(b * CC) * HW;

    // prologue: stage + store channel 0
    {
        const float* xp = xp0;
        #pragma unroll
        for (int j = 0; j < NFILL; ++j)
            regs[j] = fok[j] ? __ldg(xp + gbase0 + (fjr[j] << 7) + fcol[j]) : 0.f;
        #pragma unroll
        for (int j = 0; j < NFILL; ++j)
            tile[0][fjr[j] * TP + 8 + fcol[j]] = regs[j];
    }

    float mS[4], mW[4], mH[4];
    #pragma unroll
    for (int j = 0; j < 4; ++j) { mS[j] = -INFINITY; mW[j] = -INFINITY; mH[j] = -INFINITY; }

    for (int c = 0; c < CC; ++c) {
        const int cur = c & 1;
        // stage next channel (LDGs overlap barrier + compute)
        if (c + 1 < CC) {
            const float* xp = xp0 + (size_t)(c + 1) * HW;
            #pragma unroll
            for (int j = 0; j < NFILL; ++j)
                regs[j] = fok[j] ? __ldg(xp + gbase0 + (fjr[j] << 7) + fcol[j]) : 0.f;
        }
        __syncthreads();   // tile[cur] fully stored; tile[cur^1] fully consumed

        const float* tl = tile[cur];
        // horizontal window: cols [c4-8, c4+12) = 5 aligned float4 (data at +8)
        float in[20];
        {
            const float* hrow = &tl[(r + 5) * TP + c4];  // col c4-8 of data
            #pragma unroll
            for (int m = 0; m < 5; ++m) {
                float4 v = *(const float4*)(hrow + 4 * m);
                in[4*m+0] = v.x; in[4*m+1] = v.y; in[4*m+2] = v.z; in[4*m+3] = v.w;
            }
        }
        // vertical conv for the 4 columns
        float hv[4] = {0.f, 0.f, 0.f, 0.f};
        #pragma unroll
        for (int k = 0; k < 11; ++k) {
            float4 v = *(const float4*)(&tl[(r + k) * TP + 8 + c4]);
            float ck = sch[c * 11 + k];
            hv[0] = fmaf(v.x, ck, hv[0]);
            hv[1] = fmaf(v.y, ck, hv[1]);
            hv[2] = fmaf(v.z, ck, hv[2]);
            hv[3] = fmaf(v.w, ck, hv[3]);
        }
        // horizontal conv: output col c4+j uses in[3+j .. 13+j]
        float wv[4] = {0.f, 0.f, 0.f, 0.f};
        #pragma unroll
        for (int k = 0; k < 11; ++k) {
            float ck = scw[c * 11 + k];
            wv[0] = fmaf(in[3 + k], ck, wv[0]);
            wv[1] = fmaf(in[4 + k], ck, wv[1]);
            wv[2] = fmaf(in[5 + k], ck, wv[2]);
            wv[3] = fmaf(in[6 + k], ck, wv[3]);
        }
        const float sWc = ssW[c], sHc = ssH[c], Tc = sTv[c];
        float sc[4];
        #pragma unroll
        for (int j = 0; j < 4; ++j) {
            wv[j] *= sWc;
            hv[j] *= sHc;
            float xv = in[8 + j];
            sc[j] = (xv > Tc) ? xv : 0.f;
            mS[j] = fmaxf(mS[j], sc[j]);
            mW[j] = fmaxf(mW[j], wv[j]);
            mH[j] = fmaxf(mH[j], hv[j]);
        }

        size_t base = ((size_t)(b * 3 * CC) + c) * HW + ((size_t)grow << 7) + c4;
        *(float4*)(out + base)                       = make_float4(sc[0], sc[1], sc[2], sc[3]);
        *(float4*)(out + base + (size_t)CC * HW)     = make_float4(wv[0], wv[1], wv[2], wv[3]);
        *(float4*)(out + base + (size_t)2 * CC * HW) = make_float4(hv[0], hv[1], hv[2], hv[3]);

        if (c + 1 < CC) {
            float* tn = tile[cur ^ 1];
            #pragma unroll
            for (int j = 0; j < NFILL; ++j)
                tn[fjr[j] * TP + 8 + fcol[j]] = regs[j];
        }
    }

    size_t mb = (size_t)b * HW + ((size_t)grow << 7) + c4;
    *(float4*)(g_maxS + mb) = make_float4(mS[0], mS[1], mS[2], mS[3]);
    *(float4*)(g_maxW + mb) = make_float4(mW[0], mW[1], mW[2], mW[3]);
    *(float4*)(g_maxH + mb) = make_float4(mH[0], mH[1], mH[2], mH[3]);
}

// ---------------------------------------------------------------------------
// K2b: streaming mask pass. val = (val == channel_max) ? val : 0.
// ---------------------------------------------------------------------------
__global__ __launch_bounds__(256) void k2b_mask(float* __restrict__ out)
{
    const int t  = threadIdx.x;
    const int bc = blockIdx.y;           // 0..1023
    const int b  = bc >> 6;
    const int c  = bc & 63;
    const int p4 = blockIdx.x * 256 + t; // 0..4095
    const size_t pix = (size_t)p4 << 2;

    const size_t mb = (size_t)b * HW + pix;
    float4 mS = *(const float4*)(g_maxS + mb);
    float4 mW = *(const float4*)(g_maxW + mb);
    float4 mH = *(const float4*)(g_maxH + mb);

    size_t baseS = ((size_t)(b * 3 * CC) + c) * HW + pix;
    size_t baseW = baseS + (size_t)CC * HW;
    size_t baseH = baseS + (size_t)2 * CC * HW;

    float4 vS = *(const float4*)(out + baseS);
    float4 vW = *(const float4*)(out + baseW);
    float4 vH = *(const float4*)(out + baseH);

    vS.x = (vS.x == mS.x) ? vS.x : 0.f;
    vS.y = (vS.y == mS.y) ? vS.y : 0.f;
    vS.z = (vS.z == mS.z) ? vS.z : 0.f;
    vS.w = (vS.w == mS.w) ? vS.w : 0.f;
    vW.x = (vW.x == mW.x) ? vW.x : 0.f;
    vW.y = (vW.y == mW.y) ? vW.y : 0.f;
    vW.z = (vW.z == mW.z) ? vW.z : 0.f;
    vW.w = (vW.w == mW.w) ? vW.w : 0.f;
    vH.x = (vH.x == mH.x) ? vH.x : 0.f;
    vH.y = (vH.y == mH.y) ? vH.y : 0.f;
    vH.z = (vH.z == mH.z) ? vH.z : 0.f;
    vH.w = (vH.w == mH.w) ? vH.w : 0.f;

    *(float4*)(out + baseS) = vS;
    *(float4*)(out + baseW) = vW;
    *(float4*)(out + baseH) = vH;
}

extern "C" void kernel_launch(void* const* d_in, const int* in_sizes, int n_in,
                              void* d_out, int out_size)
{
    const float* x           = (const float*)d_in[0];
    const float* w_bbx       = (const float*)d_in[1];
    const float* w_width     = (const float*)d_in[2];
    const float* w_width_sh  = (const float*)d_in[3];
    const float* w_height    = (const float*)d_in[4];
    const float* w_height_sh = (const float*)d_in[5];
    float* out = (float*)d_out;

    k1_stats<<<BC, 256>>>(x, w_bbx, w_width, w_width_sh, w_height, w_height_sh, out);

    dim3 g2(16, BB);
    k2a_dense<<<g2, 256>>>(x, w_bbx, w_width, w_width_sh, w_height, w_height_sh, out);

    dim3 g3(16, BB * CC);
    k2b_mask<<<g3, 256>>>(out);
}

// round 5
// speedup vs baseline: 2.5373x; 1.4198x over previous
#include <cuda_runtime.h>
#include <math.h>

#define BB  16
#define CC  64
#define HH  128
#define WW  128
#define HW  (HH*WW)
#define BC  (BB*CC)

// Per-(b,c) x-space threshold T = logit(sigmoid(max x) - 0.01), from k1.
__device__ float g_T[BC];

__device__ __forceinline__ float sigmoidf_(float v) {
    return 1.0f / (1.0f + expf(-v));
}

// ---------------------------------------------------------------------------
// K1: per-(b,c) plane. max(x) -> ps, threshold T; masked sums -> bbox row.
// ---------------------------------------------------------------------------
__global__ __launch_bounds__(256) void k1_stats(
    const float* __restrict__ x,
    const float* __restrict__ w_bbx,
    const float* __restrict__ w_width,
    const float* __restrict__ w_width_sh,
    const float* __restrict__ w_height,
    const float* __restrict__ w_height_sh,
    float* __restrict__ out)
{
    const int bc = blockIdx.x;
    const int b  = bc / CC;
    const int c  = bc % CC;
    const float* __restrict__ xp = x + (size_t)bc * HW;
    const int t = threadIdx.x;

    // pass 1: plain max of x (sigmoid is monotone)
    float mx = -INFINITY;
    #pragma unroll
    for (int j = 0; j < 16; ++j) {
        float4 v = *(const float4*)(xp + 1024 * j + 4 * t);
        mx = fmaxf(fmaxf(fmaxf(mx, v.x), fmaxf(v.y, v.z)), v.w);
    }
    __shared__ float red[8];
    #pragma unroll
    for (int o = 16; o; o >>= 1) mx = fmaxf(mx, __shfl_xor_sync(0xffffffffu, mx, o));
    if ((t & 31) == 0) red[t >> 5] = mx;
    __syncthreads();
    __shared__ float sT, sps;
    if (t == 0) {
        float v = red[0];
        #pragma unroll
        for (int k = 1; k < 8; ++k) v = fmaxf(v, red[k]);
        float ps = sigmoidf_(v);
        float M  = ps - 0.01f;
        float T;
        if (M > 0.0f) {
            double dM = (double)M;
            T = (float)log(dM / (1.0 - dM));
        } else {
            T = -INFINITY;
        }
        sT = T; sps = ps;
        g_T[bc] = T;
    }
    __syncthreads();
    const float T = sT;

    float cw[11], ch[11];
    #pragma unroll
    for (int k = 0; k < 11; ++k) { cw[k] = w_width[c*11+k]; ch[k] = w_height[c*11+k]; }
    const float s0 = w_bbx[c] * 128.0f;
    const float sW = s0 * w_width_sh[c];
    const float sH = s0 * w_height_sh[c];

    // pass 2: float4 scan, scalar conv work only at (rare) masked pixels
    float S = 0.f, Sc = 0.f, Sr = 0.f, Sw = 0.f, Sh = 0.f;
    #pragma unroll
    for (int j = 0; j < 16; ++j) {
        const int i0 = 1024 * j + 4 * t;
        float4 v4 = *(const float4*)(xp + i0);
        float vv[4] = {v4.x, v4.y, v4.z, v4.w};
        if (vv[0] > T || vv[1] > T || vv[2] > T || vv[3] > T) {
            #pragma unroll
            for (int u = 0; u < 4; ++u) {
                float v = vv[u];
                if (v > T) {
                    int i = i0 + u;
                    int row = i >> 7, col = i & 127;
                    S  += v;
                    Sc += (float)col * v;
                    Sr += (float)row * v;
                    float wvv = 0.f;
                    #pragma unroll
                    for (int k = 0; k < 11; ++k) {
                        int cc2 = col - 5 + k;
                        if (cc2 >= 0 && cc2 < WW) wvv = fmaf(xp[(row << 7) + cc2], cw[k], wvv);
                    }
                    float hvv = 0.f;
                    #pragma unroll
                    for (int k = 0; k < 11; ++k) {
                        int rr = row - 5 + k;
                        if (rr >= 0 && rr < HH) hvv = fmaf(xp[(rr << 7) + col], ch[k], hvv);
                    }
                    Sw += wvv * sW * v;
                    Sh += hvv * sH * v;
                }
            }
        }
    }
    __shared__ float racc[5][8];
    #pragma unroll
    for (int o = 16; o; o >>= 1) {
        S  += __shfl_xor_sync(0xffffffffu, S,  o);
        Sc += __shfl_xor_sync(0xffffffffu, Sc, o);
        Sr += __shfl_xor_sync(0xffffffffu, Sr, o);
        Sw += __shfl_xor_sync(0xffffffffu, Sw, o);
        Sh += __shfl_xor_sync(0xffffffffu, Sh, o);
    }
    if ((t & 31) == 0) {
        int w5 = t >> 5;
        racc[0][w5] = S; racc[1][w5] = Sc; racc[2][w5] = Sr; racc[3][w5] = Sw; racc[4][w5] = Sh;
    }
    __syncthreads();
    if (t == 0) {
        float a0=0,a1=0,a2=0,a3=0,a4=0;
        #pragma unroll
        for (int k = 0; k < 8; ++k) { a0+=racc[0][k]; a1+=racc[1][k]; a2+=racc[2][k]; a3+=racc[3][k]; a4+=racc[4][k]; }
        float ws = a3 / a0, hs = a4 / a0;
        float x1 = a1 / a0 - ws * 0.5f;
        float y1 = a2 / a0 - hs * 0.5f;
        float* bb = out + (size_t)BB * 3 * CC * HW + (size_t)bc * 6;
        bb[0] = (float)b; bb[1] = x1; bb[2] = y1;
        bb[3] = x1 + ws;  bb[4] = y1 + hs; bb[5] = sps;
    }
}

// ---------------------------------------------------------------------------
// K2: fused. Channel sweep computes w/h/score and tracks (max, argmax) per
// pixel in registers; epilogue writes the dense masked output ONCE:
//   out[c] = (argmax == c) ? max : 0.
// 256 threads: r = t>>5 (8 rows), c4 = (t&31)<<2 (4 cols, 16B-aligned).
// ---------------------------------------------------------------------------
#define RG 8              // rows per block
#define TR 18             // RG + 2*5 halo
#define TP 144            // 8 zero-pad | 128 data | 8 zero-pad   (mult of 4)
#define NFILL 9           // TR*128 / 256

__global__ __launch_bounds__(256) void k2_fused(
    const float* __restrict__ x,
    const float* __restrict__ w_bbx,
    const float* __restrict__ w_width,
    const float* __restrict__ w_width_sh,
    const float* __restrict__ w_height,
    const float* __restrict__ w_height_sh,
    float* __restrict__ out)
{
    __shared__ float tile[2][TR * TP];
    __shared__ float scw[CC * 11], sch[CC * 11];
    __shared__ float ssW[CC], ssH[CC], sTv[CC];

    const int t    = threadIdx.x;         // 0..255
    const int b    = blockIdx.y;
    const int rg   = blockIdx.x;          // 0..15
    const int row0 = rg * RG;
    const int r    = t >> 5;              // 0..7
    const int c4   = (t & 31) << 2;       // 0..124, multiple of 4
    const int grow = row0 + r;

    // zero pads once for both buffers (fills never touch them)
    for (int i = t; i < TR * TP; i += 256) {
        int col = i % TP;
        if (col < 8 || col >= 136) { tile[0][i] = 0.f; tile[1][i] = 0.f; }
    }
    for (int i = t; i < CC * 11; i += 256) { scw[i] = w_width[i]; sch[i] = w_height[i]; }
    if (t < CC) {
        float s0 = w_bbx[t] * 128.0f;
        ssW[t] = s0 * w_width_sh[t];
        ssH[t] = s0 * w_height_sh[t];
        sTv[t] = g_T[b * CC + t];
    }

    // fill staging: NFILL elements per thread cover TR x 128
    int   fjr[NFILL], fcol[NFILL];
    bool  fok[NFILL];
    #pragma unroll
    for (int j = 0; j < NFILL; ++j) {
        int idx = t + j * 256;
        fjr[j]  = idx >> 7;
        fcol[j] = idx & 127;
        int gr  = row0 - 5 + fjr[j];
        fok[j]  = (gr >= 0 && gr < HH);
    }
    const int gbase0 = (row0 - 5) << 7;   // global offset of tile row 0 (may be negative)

    float regs[NFILL];
    const float* xp0 = x + (size_t)(b * CC) * HW;

    // prologue: stage + store channel 0
    {
        const float* xp = xp0;
        #pragma unroll
        for (int j = 0; j < NFILL; ++j)
            regs[j] = fok[j] ? __ldg(xp + gbase0 + (fjr[j] << 7) + fcol[j]) : 0.f;
        #pragma unroll
        for (int j = 0; j < NFILL; ++j)
            tile[0][fjr[j] * TP + 8 + fcol[j]] = regs[j];
    }

    float mS[4], mW[4], mH[4];
    int   iS[4], iW[4], iH[4];
    #pragma unroll
    for (int j = 0; j < 4; ++j) {
        mS[j] = -INFINITY; mW[j] = -INFINITY; mH[j] = -INFINITY;
        iS[j] = 0; iW[j] = 0; iH[j] = 0;
    }

    for (int c = 0; c < CC; ++c) {
        const int cur = c & 1;
        // stage next channel (LDGs overlap barrier + compute)
        if (c + 1 < CC) {
            const float* xp = xp0 + (size_t)(c + 1) * HW;
            #pragma unroll
            for (int j = 0; j < NFILL; ++j)
                regs[j] = fok[j] ? __ldg(xp + gbase0 + (fjr[j] << 7) + fcol[j]) : 0.f;
        }
        __syncthreads();   // tile[cur] fully stored; tile[cur^1] fully consumed

        const float* tl = tile[cur];
        // horizontal window: cols [c4-8, c4+12) = 5 aligned float4 (data at +8)
        float in[20];
        {
            const float* hrow = &tl[(r + 5) * TP + c4];  // col c4-8 of data
            #pragma unroll
            for (int m = 0; m < 5; ++m) {
                float4 v = *(const float4*)(hrow + 4 * m);
                in[4*m+0] = v.x; in[4*m+1] = v.y; in[4*m+2] = v.z; in[4*m+3] = v.w;
            }
        }
        // vertical conv for the 4 columns
        float hv[4] = {0.f, 0.f, 0.f, 0.f};
        #pragma unroll
        for (int k = 0; k < 11; ++k) {
            float4 v = *(const float4*)(&tl[(r + k) * TP + 8 + c4]);
            float ck = sch[c * 11 + k];
            hv[0] = fmaf(v.x, ck, hv[0]);
            hv[1] = fmaf(v.y, ck, hv[1]);
            hv[2] = fmaf(v.z, ck, hv[2]);
            hv[3] = fmaf(v.w, ck, hv[3]);
        }
        // horizontal conv: output col c4+j uses in[3+j .. 13+j]
        float wv[4] = {0.f, 0.f, 0.f, 0.f};
        #pragma unroll
        for (int k = 0; k < 11; ++k) {
            float ck = scw[c * 11 + k];
            wv[0] = fmaf(in[3 + k], ck, wv[0]);
            wv[1] = fmaf(in[4 + k], ck, wv[1]);
            wv[2] = fmaf(in[5 + k], ck, wv[2]);
            wv[3] = fmaf(in[6 + k], ck, wv[3]);
        }
        const float sWc = ssW[c], sHc = ssH[c], Tc = sTv[c];
        #pragma unroll
        for (int j = 0; j < 4; ++j) {
            float w_ = wv[j] * sWc;
            float h_ = hv[j] * sHc;
            float xv = in[8 + j];
            float s_ = (xv > Tc) ? xv : 0.f;
            if (s_ > mS[j]) { mS[j] = s_; iS[j] = c; }
            if (w_ > mW[j]) { mW[j] = w_; iW[j] = c; }
            if (h_ > mH[j]) { mH[j] = h_; iH[j] = c; }
        }

        if (c + 1 < CC) {
            float* tn = tile[cur ^ 1];
            #pragma unroll
            for (int j = 0; j < NFILL; ++j)
                tn[fjr[j] * TP + 8 + fcol[j]] = regs[j];
        }
    }

    // epilogue: dense masked write, one pass over all channels
    const size_t ob = (size_t)(b * 3 * CC) * HW + ((size_t)grow << 7) + c4;
    float* oS = out + ob;
    float* oW = oS + (size_t)CC * HW;
    float* oH = oS + (size_t)2 * CC * HW;
    for (int c = 0; c < CC; ++c) {
        float4 vS = make_float4(iS[0]==c ? mS[0] : 0.f, iS[1]==c ? mS[1] : 0.f,
                                iS[2]==c ? mS[2] : 0.f, iS[3]==c ? mS[3] : 0.f);
        float4 vW = make_float4(iW[0]==c ? mW[0] : 0.f, iW[1]==c ? mW[1] : 0.f,
                                iW[2]==c ? mW[2] : 0.f, iW[3]==c ? mW[3] : 0.f);
        float4 vH = make_float4(iH[0]==c ? mH[0] : 0.f, iH[1]==c ? mH[1] : 0.f,
                                iH[2]==c ? mH[2] : 0.f, iH[3]==c ? mH[3] : 0.f);
        const size_t off = (size_t)c * HW;
        __stcs((float4*)(oS + off), vS);
        __stcs((float4*)(oW + off), vW);
        __stcs((float4*)(oH + off), vH);
    }
}

extern "C" void kernel_launch(void* const* d_in, const int* in_sizes, int n_in,
                              void* d_out, int out_size)
{
    const float* x           = (const float*)d_in[0];
    const float* w_bbx       = (const float*)d_in[1];
    const float* w_width     = (const float*)d_in[2];
    const float* w_width_sh  = (const float*)d_in[3];
    const float* w_height    = (const float*)d_in[4];
    const float* w_height_sh = (const float*)d_in[5];
    float* out = (float*)d_out;

    k1_stats<<<BC, 256>>>(x, w_bbx, w_width, w_width_sh, w_height, w_height_sh, out);

    dim3 g2(16, BB);
    k2_fused<<<g2, 256>>>(x, w_bbx, w_width, w_width_sh, w_height, w_height_sh, out);
}